// round 5
// baseline (speedup 1.0000x reference)
#include <cuda_runtime.h>

// ---------------------------------------------------------------------------
// NonlocalBlock: fused 1x1-conv non-local block, fp32 SGEMM pipeline.
// Shapes: N=16, C=256, H=W=64 (S=4096), width=128, planes=256.
//
// Pipeline (all GEMMs, 128x128 block tiles, 256 threads, 8x8 microtiles):
//   Z  : zero kv accumulator
//   A  : theta/phi/g = relu(bn(W[128x256] @ x[256xS])), stored pixel-major [n][s][c]
//   B  : kv[n] = sum_s phi[s][:]^T g[s][:]  (split-K=16, atomicAdd)
//   C1 : y[n][ch][q*128+d] = sum_c theta[n][ch*32+q][c] * kv[n][c][d]
//        (this IS the torch reshape [n,S,128]->[n,128,64,64])
//   C2 : out = relu(bn4(w_zeta[256x128] @ y) + x)
// ---------------------------------------------------------------------------

#define BN_EPS 1e-5f

// scratch (device globals: allocation-free per harness rules)
__device__ float g_theta[16 * 4096 * 128];  // [n][s][c]
__device__ float g_phi  [16 * 4096 * 128];  // [n][s][c]
__device__ float g_gbuf [16 * 4096 * 128];  // [n][s][c]
__device__ float g_kv   [16 * 128 * 128];   // [n][c][d]
__device__ float g_y    [16 * 128 * 4096];  // [n][ch][pix]

// ---------------------------------------------------------------------------
__global__ void zero_kv_kernel() {
    int idx = blockIdx.x * blockDim.x + threadIdx.x;
    const int total = 16 * 128 * 128;
    for (int i = idx; i < total; i += gridDim.x * blockDim.x) g_kv[i] = 0.0f;
}

// ---------------------------------------------------------------------------
// Kernel A: projections. grid (512 pixel tiles, 3 projections), 256 threads.
// C_out[i][j] = sum_k W[i][k] * x[n][k][p0+j], then bn+relu, store [s][c].
__global__ __launch_bounds__(256) void proj_kernel(
    const float* __restrict__ x,
    const float* __restrict__ w0, const float* __restrict__ w1, const float* __restrict__ w2,
    const float* __restrict__ g0, const float* __restrict__ b0, const float* __restrict__ m0, const float* __restrict__ v0,
    const float* __restrict__ g1, const float* __restrict__ b1, const float* __restrict__ m1, const float* __restrict__ v1,
    const float* __restrict__ g2, const float* __restrict__ b2, const float* __restrict__ m2, const float* __restrict__ v2)
{
    const int t  = blockIdx.x;       // 0..511
    const int mb = blockIdx.y;       // 0 theta, 1 phi, 2 g
    const int n  = t >> 5;
    const int q  = t & 31;

    const float* W  = (mb == 0) ? w0 : (mb == 1) ? w1 : w2;
    const float* gm = (mb == 0) ? g0 : (mb == 1) ? g1 : g2;
    const float* bt = (mb == 0) ? b0 : (mb == 1) ? b1 : b2;
    const float* mn = (mb == 0) ? m0 : (mb == 1) ? m1 : m2;
    const float* vr = (mb == 0) ? v0 : (mb == 1) ? v1 : v2;
    float* outb = (mb == 0) ? g_theta : (mb == 1) ? g_phi : g_gbuf;

    __shared__ float As[8][129];   // As[k][i] = W[i][kk+k]  (padded: scattered stores)
    __shared__ float Bs[8][128];   // Bs[k][j] = x[n][kk+k][p0+j]

    const int tid = threadIdx.x;
    const int tx = tid & 15, ty = tid >> 4;

    float acc[8][8];
    #pragma unroll
    for (int i = 0; i < 8; i++)
        #pragma unroll
        for (int j = 0; j < 8; j++) acc[i][j] = 0.0f;

    const float* xblk = x + (size_t)n * 256 * 4096 + q * 128;

    for (int kk = 0; kk < 256; kk += 8) {
        { // A tile (transpose load)
            int i = tid >> 1, kq = (tid & 1) * 4;
            float4 va = *reinterpret_cast<const float4*>(W + i * 256 + kk + kq);
            As[kq + 0][i] = va.x; As[kq + 1][i] = va.y;
            As[kq + 2][i] = va.z; As[kq + 3][i] = va.w;
        }
        { // B tile (coalesced)
            int k = tid >> 5, j4 = (tid & 31) * 4;
            *reinterpret_cast<float4*>(&Bs[k][j4]) =
                *reinterpret_cast<const float4*>(xblk + (size_t)(kk + k) * 4096 + j4);
        }
        __syncthreads();
        #pragma unroll
        for (int k = 0; k < 8; k++) {
            float a[8], b[8];
            #pragma unroll
            for (int u = 0; u < 4; u++) {
                a[u]     = As[k][ty * 4 + u];
                a[4 + u] = As[k][64 + ty * 4 + u];
                b[u]     = Bs[k][tx * 4 + u];
                b[4 + u] = Bs[k][64 + tx * 4 + u];
            }
            #pragma unroll
            for (int i = 0; i < 8; i++)
                #pragma unroll
                for (int j = 0; j < 8; j++) acc[i][j] += a[i] * b[j];
        }
        __syncthreads();
    }

    // bn scale/shift per owned row (channel)
    float scale[8], shift[8];
    #pragma unroll
    for (int u = 0; u < 8; u++) {
        int i = (u < 4) ? (ty * 4 + u) : (64 + ty * 4 + (u - 4));
        float s = gm[i] * rsqrtf(vr[i] + BN_EPS);
        scale[u] = s;
        shift[u] = bt[i] - mn[i] * s;
    }

    // store: pixel-major [s][c]; per pixel-column write two float4 in c
    float* ob = outb + ((size_t)n * 4096 + (size_t)q * 128) * 128;
    #pragma unroll
    for (int jj = 0; jj < 8; jj++) {
        int j = (jj < 4) ? (tx * 4 + jj) : (64 + tx * 4 + (jj - 4));
        float4 v0, v1;
        v0.x = fmaxf(acc[0][jj] * scale[0] + shift[0], 0.0f);
        v0.y = fmaxf(acc[1][jj] * scale[1] + shift[1], 0.0f);
        v0.z = fmaxf(acc[2][jj] * scale[2] + shift[2], 0.0f);
        v0.w = fmaxf(acc[3][jj] * scale[3] + shift[3], 0.0f);
        v1.x = fmaxf(acc[4][jj] * scale[4] + shift[4], 0.0f);
        v1.y = fmaxf(acc[5][jj] * scale[5] + shift[5], 0.0f);
        v1.z = fmaxf(acc[6][jj] * scale[6] + shift[6], 0.0f);
        v1.w = fmaxf(acc[7][jj] * scale[7] + shift[7], 0.0f);
        *reinterpret_cast<float4*>(ob + (size_t)j * 128 + ty * 4)      = v0;
        *reinterpret_cast<float4*>(ob + (size_t)j * 128 + 64 + ty * 4) = v1;
    }
}

// ---------------------------------------------------------------------------
// Kernel B: kv[n][c][d] = sum_s phi[n][s][c] * g[n][s][d]. grid (16 n, 16 splits).
__global__ __launch_bounds__(256) void kv_kernel()
{
    const int n  = blockIdx.x;
    const int s0 = blockIdx.y * 256;

    __shared__ float As[8][128];   // phi rows (K-major already)
    __shared__ float Bs[8][128];   // g rows

    const int tid = threadIdx.x;
    const int tx = tid & 15, ty = tid >> 4;

    float acc[8][8];
    #pragma unroll
    for (int i = 0; i < 8; i++)
        #pragma unroll
        for (int j = 0; j < 8; j++) acc[i][j] = 0.0f;

    const float* phib = g_phi  + ((size_t)n * 4096 + s0) * 128;
    const float* gb   = g_gbuf + ((size_t)n * 4096 + s0) * 128;

    for (int kk = 0; kk < 256; kk += 8) {
        int k = tid >> 5, c4 = (tid & 31) * 4;
        *reinterpret_cast<float4*>(&As[k][c4]) =
            *reinterpret_cast<const float4*>(phib + (size_t)(kk + k) * 128 + c4);
        *reinterpret_cast<float4*>(&Bs[k][c4]) =
            *reinterpret_cast<const float4*>(gb + (size_t)(kk + k) * 128 + c4);
        __syncthreads();
        #pragma unroll
        for (int k2 = 0; k2 < 8; k2++) {
            float a[8], b[8];
            #pragma unroll
            for (int u = 0; u < 4; u++) {
                a[u]     = As[k2][ty * 4 + u];
                a[4 + u] = As[k2][64 + ty * 4 + u];
                b[u]     = Bs[k2][tx * 4 + u];
                b[4 + u] = Bs[k2][64 + tx * 4 + u];
            }
            #pragma unroll
            for (int i = 0; i < 8; i++)
                #pragma unroll
                for (int j = 0; j < 8; j++) acc[i][j] += a[i] * b[j];
        }
        __syncthreads();
    }

    float* kvp = g_kv + (size_t)n * 16384;
    #pragma unroll
    for (int ii = 0; ii < 8; ii++) {
        int i = (ii < 4) ? (ty * 4 + ii) : (64 + ty * 4 + (ii - 4));
        #pragma unroll
        for (int jj = 0; jj < 8; jj++) {
            int j = (jj < 4) ? (tx * 4 + jj) : (64 + tx * 4 + (jj - 4));
            atomicAdd(&kvp[i * 128 + j], acc[ii][jj]);
        }
    }
}

// ---------------------------------------------------------------------------
// Kernel C1: y[n][ch][q*128+d] = sum_c theta[n][ch*32+q][c] * kv[n][c][d]. grid 512.
__global__ __launch_bounds__(256) void att_kernel()
{
    const int t = blockIdx.x;
    const int n = t >> 5;
    const int q = t & 31;

    __shared__ float Ta[8][129];   // Ta[k][ch] = theta[n][ch*32+q][c0+k]
    __shared__ float Kb[8][128];   // Kb[k][d]  = kv[n][c0+k][d]

    const int tid = threadIdx.x;
    const int tx = tid & 15, ty = tid >> 4;

    float acc[8][8];
    #pragma unroll
    for (int i = 0; i < 8; i++)
        #pragma unroll
        for (int j = 0; j < 8; j++) acc[i][j] = 0.0f;

    const float* thb = g_theta + (size_t)n * 4096 * 128;
    const float* kvb = g_kv + (size_t)n * 16384;

    for (int c0 = 0; c0 < 128; c0 += 8) {
        { // theta gather+transpose: ch = tid/2, 4 consecutive c
            int ch = tid >> 1, kq = (tid & 1) * 4;
            int s = ch * 32 + q;
            float4 va = *reinterpret_cast<const float4*>(thb + (size_t)s * 128 + c0 + kq);
            Ta[kq + 0][ch] = va.x; Ta[kq + 1][ch] = va.y;
            Ta[kq + 2][ch] = va.z; Ta[kq + 3][ch] = va.w;
        }
        {
            int k = tid >> 5, d4 = (tid & 31) * 4;
            *reinterpret_cast<float4*>(&Kb[k][d4]) =
                *reinterpret_cast<const float4*>(kvb + (size_t)(c0 + k) * 128 + d4);
        }
        __syncthreads();
        #pragma unroll
        for (int k = 0; k < 8; k++) {
            float a[8], b[8];
            #pragma unroll
            for (int u = 0; u < 4; u++) {
                a[u]     = Ta[k][ty * 4 + u];
                a[4 + u] = Ta[k][64 + ty * 4 + u];
                b[u]     = Kb[k][tx * 4 + u];
                b[4 + u] = Kb[k][64 + tx * 4 + u];
            }
            #pragma unroll
            for (int i = 0; i < 8; i++)
                #pragma unroll
                for (int j = 0; j < 8; j++) acc[i][j] += a[i] * b[j];
        }
        __syncthreads();
    }

    float* yb = g_y + (size_t)n * 128 * 4096 + q * 128;
    #pragma unroll
    for (int ii = 0; ii < 8; ii++) {
        int ch = (ii < 4) ? (ty * 4 + ii) : (64 + ty * 4 + (ii - 4));
        float4 v0 = make_float4(acc[ii][0], acc[ii][1], acc[ii][2], acc[ii][3]);
        float4 v1 = make_float4(acc[ii][4], acc[ii][5], acc[ii][6], acc[ii][7]);
        *reinterpret_cast<float4*>(yb + (size_t)ch * 4096 + tx * 4)      = v0;
        *reinterpret_cast<float4*>(yb + (size_t)ch * 4096 + 64 + tx * 4) = v1;
    }
}

// ---------------------------------------------------------------------------
// Kernel C2: out = relu(bn4(w_zeta @ y) + x). grid (512 tiles, 2 co halves).
__global__ __launch_bounds__(256) void zeta_kernel(
    const float* __restrict__ w_zeta, const float* __restrict__ x,
    const float* __restrict__ g4, const float* __restrict__ b4,
    const float* __restrict__ m4, const float* __restrict__ v4,
    float* __restrict__ out)
{
    const int t  = blockIdx.x;
    const int mb = blockIdx.y;   // output-channel half
    const int n  = t >> 5;
    const int q  = t & 31;

    __shared__ float As[8][129];   // As[k][i] = w_zeta[mb*128+i][kk+k]
    __shared__ float Bs[8][128];   // Bs[k][j] = y[n][kk+k][q*128+j]

    const int tid = threadIdx.x;
    const int tx = tid & 15, ty = tid >> 4;

    float acc[8][8];
    #pragma unroll
    for (int i = 0; i < 8; i++)
        #pragma unroll
        for (int j = 0; j < 8; j++) acc[i][j] = 0.0f;

    const float* yb = g_y + (size_t)n * 128 * 4096 + q * 128;

    for (int kk = 0; kk < 128; kk += 8) {
        {
            int i = tid >> 1, kq = (tid & 1) * 4;
            float4 va = *reinterpret_cast<const float4*>(
                w_zeta + (size_t)(mb * 128 + i) * 128 + kk + kq);
            As[kq + 0][i] = va.x; As[kq + 1][i] = va.y;
            As[kq + 2][i] = va.z; As[kq + 3][i] = va.w;
        }
        {
            int k = tid >> 5, j4 = (tid & 31) * 4;
            *reinterpret_cast<float4*>(&Bs[k][j4]) =
                *reinterpret_cast<const float4*>(yb + (size_t)(kk + k) * 4096 + j4);
        }
        __syncthreads();
        #pragma unroll
        for (int k = 0; k < 8; k++) {
            float a[8], b[8];
            #pragma unroll
            for (int u = 0; u < 4; u++) {
                a[u]     = As[k][ty * 4 + u];
                a[4 + u] = As[k][64 + ty * 4 + u];
                b[u]     = Bs[k][tx * 4 + u];
                b[4 + u] = Bs[k][64 + tx * 4 + u];
            }
            #pragma unroll
            for (int i = 0; i < 8; i++)
                #pragma unroll
                for (int j = 0; j < 8; j++) acc[i][j] += a[i] * b[j];
        }
        __syncthreads();
    }

    float scale[8], shift[8];
    #pragma unroll
    for (int u = 0; u < 8; u++) {
        int i = (u < 4) ? (ty * 4 + u) : (64 + ty * 4 + (u - 4));
        int co = mb * 128 + i;
        float s = g4[co] * rsqrtf(v4[co] + BN_EPS);
        scale[u] = s;
        shift[u] = b4[co] - m4[co] * s;
    }

    #pragma unroll
    for (int ii = 0; ii < 8; ii++) {
        int i  = (ii < 4) ? (ty * 4 + ii) : (64 + ty * 4 + (ii - 4));
        int co = mb * 128 + i;
        size_t base = ((size_t)n * 256 + co) * 4096 + q * 128;
        #pragma unroll
        for (int half = 0; half < 2; half++) {
            int j0 = half * 64 + tx * 4;
            float4 xv = *reinterpret_cast<const float4*>(x + base + j0);
            float4 r;
            r.x = fmaxf(acc[ii][half * 4 + 0] * scale[ii] + shift[ii] + xv.x, 0.0f);
            r.y = fmaxf(acc[ii][half * 4 + 1] * scale[ii] + shift[ii] + xv.y, 0.0f);
            r.z = fmaxf(acc[ii][half * 4 + 2] * scale[ii] + shift[ii] + xv.z, 0.0f);
            r.w = fmaxf(acc[ii][half * 4 + 3] * scale[ii] + shift[ii] + xv.w, 0.0f);
            *reinterpret_cast<float4*>(out + base + j0) = r;
        }
    }
}

// ---------------------------------------------------------------------------
extern "C" void kernel_launch(void* const* d_in, const int* in_sizes, int n_in,
                              void* d_out, int out_size)
{
    const float* x       = (const float*)d_in[0];
    const float* w_theta = (const float*)d_in[1];
    const float* w_phi   = (const float*)d_in[2];
    const float* w_g     = (const float*)d_in[3];
    const float* w_zeta  = (const float*)d_in[4];
    const float* bn1g = (const float*)d_in[5],  *bn1b = (const float*)d_in[6];
    const float* bn1m = (const float*)d_in[7],  *bn1v = (const float*)d_in[8];
    const float* bn2g = (const float*)d_in[9],  *bn2b = (const float*)d_in[10];
    const float* bn2m = (const float*)d_in[11], *bn2v = (const float*)d_in[12];
    const float* bn3g = (const float*)d_in[13], *bn3b = (const float*)d_in[14];
    const float* bn3m = (const float*)d_in[15], *bn3v = (const float*)d_in[16];
    const float* bn4g = (const float*)d_in[17], *bn4b = (const float*)d_in[18];
    const float* bn4m = (const float*)d_in[19], *bn4v = (const float*)d_in[20];
    float* out = (float*)d_out;

    zero_kv_kernel<<<256, 256>>>();
    proj_kernel<<<dim3(512, 3), 256>>>(x, w_theta, w_phi, w_g,
                                       bn1g, bn1b, bn1m, bn1v,
                                       bn2g, bn2b, bn2m, bn2v,
                                       bn3g, bn3b, bn3m, bn3v);
    kv_kernel<<<dim3(16, 16), 256>>>();
    att_kernel<<<512, 256>>>();
    zeta_kernel<<<dim3(512, 2), 256>>>(w_zeta, x, bn4g, bn4b, bn4m, bn4v, out);
}

// round 6
// speedup vs baseline: 1.0071x; 1.0071x over previous
#include <cuda_runtime.h>

// ---------------------------------------------------------------------------
// NonlocalBlock: fused 1x1-conv non-local block, fp32 SGEMM pipeline.
// Shapes: N=16, C=256, H=W=64 (S=4096), width=128, planes=256.
//
// Pipeline (all GEMMs, 128x128 block tiles, 256 threads, 8x8 microtiles):
//   Z  : zero kv accumulator
//   A  : theta/phi/g = relu(bn(W[128x256] @ x[256xS])), stored pixel-major [n][s][c]
//   B  : kv[n] = sum_s phi[s][:]^T g[s][:]  (split-K=16, atomicAdd)
//   C1 : y[n][ch][q*128+d] = sum_c theta[n][ch*32+q][c] * kv[n][c][d]
//        (this IS the torch reshape [n,S,128]->[n,128,64,64])
//   C2 : out = relu(bn4(w_zeta[256x128] @ y) + x)
// ---------------------------------------------------------------------------

#define BN_EPS 1e-5f

// scratch (device globals: allocation-free per harness rules)
__device__ float g_theta[16 * 4096 * 128];  // [n][s][c]
__device__ float g_phi  [16 * 4096 * 128];  // [n][s][c]
__device__ float g_gbuf [16 * 4096 * 128];  // [n][s][c]
__device__ float g_kv   [16 * 128 * 128];   // [n][c][d]
__device__ float g_y    [16 * 128 * 4096];  // [n][ch][pix]

// ---------------------------------------------------------------------------
__global__ void zero_kv_kernel() {
    int idx = blockIdx.x * blockDim.x + threadIdx.x;
    const int total = 16 * 128 * 128;
    for (int i = idx; i < total; i += gridDim.x * blockDim.x) g_kv[i] = 0.0f;
}

// ---------------------------------------------------------------------------
// Kernel A: projections. grid (512 pixel tiles, 3 projections), 256 threads.
// C_out[i][j] = sum_k W[i][k] * x[n][k][p0+j], then bn+relu, store [s][c].
__global__ __launch_bounds__(256) void proj_kernel(
    const float* __restrict__ x,
    const float* __restrict__ w0, const float* __restrict__ w1, const float* __restrict__ w2,
    const float* __restrict__ g0, const float* __restrict__ b0, const float* __restrict__ m0, const float* __restrict__ v0,
    const float* __restrict__ g1, const float* __restrict__ b1, const float* __restrict__ m1, const float* __restrict__ v1,
    const float* __restrict__ g2, const float* __restrict__ b2, const float* __restrict__ m2, const float* __restrict__ v2)
{
    const int t  = blockIdx.x;       // 0..511
    const int mb = blockIdx.y;       // 0 theta, 1 phi, 2 g
    const int n  = t >> 5;
    const int q  = t & 31;

    const float* W  = (mb == 0) ? w0 : (mb == 1) ? w1 : w2;
    const float* gm = (mb == 0) ? g0 : (mb == 1) ? g1 : g2;
    const float* bt = (mb == 0) ? b0 : (mb == 1) ? b1 : b2;
    const float* mn = (mb == 0) ? m0 : (mb == 1) ? m1 : m2;
    const float* vr = (mb == 0) ? v0 : (mb == 1) ? v1 : v2;
    float* outb = (mb == 0) ? g_theta : (mb == 1) ? g_phi : g_gbuf;

    __shared__ float As[8][129];   // As[k][i] = W[i][kk+k]  (padded: scattered stores)
    __shared__ float Bs[8][128];   // Bs[k][j] = x[n][kk+k][p0+j]

    const int tid = threadIdx.x;
    const int tx = tid & 15, ty = tid >> 4;

    float acc[8][8];
    #pragma unroll
    for (int i = 0; i < 8; i++)
        #pragma unroll
        for (int j = 0; j < 8; j++) acc[i][j] = 0.0f;

    const float* xblk = x + (size_t)n * 256 * 4096 + q * 128;

    for (int kk = 0; kk < 256; kk += 8) {
        { // A tile (transpose load)
            int i = tid >> 1, kq = (tid & 1) * 4;
            float4 va = *reinterpret_cast<const float4*>(W + i * 256 + kk + kq);
            As[kq + 0][i] = va.x; As[kq + 1][i] = va.y;
            As[kq + 2][i] = va.z; As[kq + 3][i] = va.w;
        }
        { // B tile (coalesced)
            int k = tid >> 5, j4 = (tid & 31) * 4;
            *reinterpret_cast<float4*>(&Bs[k][j4]) =
                *reinterpret_cast<const float4*>(xblk + (size_t)(kk + k) * 4096 + j4);
        }
        __syncthreads();
        #pragma unroll
        for (int k = 0; k < 8; k++) {
            float a[8], b[8];
            #pragma unroll
            for (int u = 0; u < 4; u++) {
                a[u]     = As[k][ty * 4 + u];
                a[4 + u] = As[k][64 + ty * 4 + u];
                b[u]     = Bs[k][tx * 4 + u];
                b[4 + u] = Bs[k][64 + tx * 4 + u];
            }
            #pragma unroll
            for (int i = 0; i < 8; i++)
                #pragma unroll
                for (int j = 0; j < 8; j++) acc[i][j] += a[i] * b[j];
        }
        __syncthreads();
    }

    // bn scale/shift per owned row (channel)
    float scale[8], shift[8];
    #pragma unroll
    for (int u = 0; u < 8; u++) {
        int i = (u < 4) ? (ty * 4 + u) : (64 + ty * 4 + (u - 4));
        float s = gm[i] * rsqrtf(vr[i] + BN_EPS);
        scale[u] = s;
        shift[u] = bt[i] - mn[i] * s;
    }

    // store: pixel-major [s][c]; per pixel-column write two float4 in c
    float* ob = outb + ((size_t)n * 4096 + (size_t)q * 128) * 128;
    #pragma unroll
    for (int jj = 0; jj < 8; jj++) {
        int j = (jj < 4) ? (tx * 4 + jj) : (64 + tx * 4 + (jj - 4));
        float4 v0, v1;
        v0.x = fmaxf(acc[0][jj] * scale[0] + shift[0], 0.0f);
        v0.y = fmaxf(acc[1][jj] * scale[1] + shift[1], 0.0f);
        v0.z = fmaxf(acc[2][jj] * scale[2] + shift[2], 0.0f);
        v0.w = fmaxf(acc[3][jj] * scale[3] + shift[3], 0.0f);
        v1.x = fmaxf(acc[4][jj] * scale[4] + shift[4], 0.0f);
        v1.y = fmaxf(acc[5][jj] * scale[5] + shift[5], 0.0f);
        v1.z = fmaxf(acc[6][jj] * scale[6] + shift[6], 0.0f);
        v1.w = fmaxf(acc[7][jj] * scale[7] + shift[7], 0.0f);
        *reinterpret_cast<float4*>(ob + (size_t)j * 128 + ty * 4)      = v0;
        *reinterpret_cast<float4*>(ob + (size_t)j * 128 + 64 + ty * 4) = v1;
    }
}

// ---------------------------------------------------------------------------
// Kernel B: kv[n][c][d] = sum_s phi[n][s][c] * g[n][s][d]. grid (16 n, 16 splits).
__global__ __launch_bounds__(256) void kv_kernel()
{
    const int n  = blockIdx.x;
    const int s0 = blockIdx.y * 256;

    __shared__ float As[8][128];   // phi rows (K-major already)
    __shared__ float Bs[8][128];   // g rows

    const int tid = threadIdx.x;
    const int tx = tid & 15, ty = tid >> 4;

    float acc[8][8];
    #pragma unroll
    for (int i = 0; i < 8; i++)
        #pragma unroll
        for (int j = 0; j < 8; j++) acc[i][j] = 0.0f;

    const float* phib = g_phi  + ((size_t)n * 4096 + s0) * 128;
    const float* gb   = g_gbuf + ((size_t)n * 4096 + s0) * 128;

    for (int kk = 0; kk < 256; kk += 8) {
        int k = tid >> 5, c4 = (tid & 31) * 4;
        *reinterpret_cast<float4*>(&As[k][c4]) =
            *reinterpret_cast<const float4*>(phib + (size_t)(kk + k) * 128 + c4);
        *reinterpret_cast<float4*>(&Bs[k][c4]) =
            *reinterpret_cast<const float4*>(gb + (size_t)(kk + k) * 128 + c4);
        __syncthreads();
        #pragma unroll
        for (int k2 = 0; k2 < 8; k2++) {
            float a[8], b[8];
            #pragma unroll
            for (int u = 0; u < 4; u++) {
                a[u]     = As[k2][ty * 4 + u];
                a[4 + u] = As[k2][64 + ty * 4 + u];
                b[u]     = Bs[k2][tx * 4 + u];
                b[4 + u] = Bs[k2][64 + tx * 4 + u];
            }
            #pragma unroll
            for (int i = 0; i < 8; i++)
                #pragma unroll
                for (int j = 0; j < 8; j++) acc[i][j] += a[i] * b[j];
        }
        __syncthreads();
    }

    float* kvp = g_kv + (size_t)n * 16384;
    #pragma unroll
    for (int ii = 0; ii < 8; ii++) {
        int i = (ii < 4) ? (ty * 4 + ii) : (64 + ty * 4 + (ii - 4));
        #pragma unroll
        for (int jj = 0; jj < 8; jj++) {
            int j = (jj < 4) ? (tx * 4 + jj) : (64 + tx * 4 + (jj - 4));
            atomicAdd(&kvp[i * 128 + j], acc[ii][jj]);
        }
    }
}

// ---------------------------------------------------------------------------
// Kernel C1: y[n][ch][q*128+d] = sum_c theta[n][ch*32+q][c] * kv[n][c][d]. grid 512.
__global__ __launch_bounds__(256) void att_kernel()
{
    const int t = blockIdx.x;
    const int n = t >> 5;
    const int q = t & 31;

    __shared__ float Ta[8][129];   // Ta[k][ch] = theta[n][ch*32+q][c0+k]
    __shared__ float Kb[8][128];   // Kb[k][d]  = kv[n][c0+k][d]

    const int tid = threadIdx.x;
    const int tx = tid & 15, ty = tid >> 4;

    float acc[8][8];
    #pragma unroll
    for (int i = 0; i < 8; i++)
        #pragma unroll
        for (int j = 0; j < 8; j++) acc[i][j] = 0.0f;

    const float* thb = g_theta + (size_t)n * 4096 * 128;
    const float* kvb = g_kv + (size_t)n * 16384;

    for (int c0 = 0; c0 < 128; c0 += 8) {
        { // theta gather+transpose: ch = tid/2, 4 consecutive c
            int ch = tid >> 1, kq = (tid & 1) * 4;
            int s = ch * 32 + q;
            float4 va = *reinterpret_cast<const float4*>(thb + (size_t)s * 128 + c0 + kq);
            Ta[kq + 0][ch] = va.x; Ta[kq + 1][ch] = va.y;
            Ta[kq + 2][ch] = va.z; Ta[kq + 3][ch] = va.w;
        }
        {
            int k = tid >> 5, d4 = (tid & 31) * 4;
            *reinterpret_cast<float4*>(&Kb[k][d4]) =
                *reinterpret_cast<const float4*>(kvb + (size_t)(c0 + k) * 128 + d4);
        }
        __syncthreads();
        #pragma unroll
        for (int k = 0; k < 8; k++) {
            float a[8], b[8];
            #pragma unroll
            for (int u = 0; u < 4; u++) {
                a[u]     = Ta[k][ty * 4 + u];
                a[4 + u] = Ta[k][64 + ty * 4 + u];
                b[u]     = Kb[k][tx * 4 + u];
                b[4 + u] = Kb[k][64 + tx * 4 + u];
            }
            #pragma unroll
            for (int i = 0; i < 8; i++)
                #pragma unroll
                for (int j = 0; j < 8; j++) acc[i][j] += a[i] * b[j];
        }
        __syncthreads();
    }

    float* yb = g_y + (size_t)n * 128 * 4096 + q * 128;
    #pragma unroll
    for (int ii = 0; ii < 8; ii++) {
        int ch = (ii < 4) ? (ty * 4 + ii) : (64 + ty * 4 + (ii - 4));
        float4 v0 = make_float4(acc[ii][0], acc[ii][1], acc[ii][2], acc[ii][3]);
        float4 v1 = make_float4(acc[ii][4], acc[ii][5], acc[ii][6], acc[ii][7]);
        *reinterpret_cast<float4*>(yb + (size_t)ch * 4096 + tx * 4)      = v0;
        *reinterpret_cast<float4*>(yb + (size_t)ch * 4096 + 64 + tx * 4) = v1;
    }
}

// ---------------------------------------------------------------------------
// Kernel C2: out = relu(bn4(w_zeta @ y) + x). grid (512 tiles, 2 co halves).
__global__ __launch_bounds__(256) void zeta_kernel(
    const float* __restrict__ w_zeta, const float* __restrict__ x,
    const float* __restrict__ g4, const float* __restrict__ b4,
    const float* __restrict__ m4, const float* __restrict__ v4,
    float* __restrict__ out)
{
    const int t  = blockIdx.x;
    const int mb = blockIdx.y;   // output-channel half
    const int n  = t >> 5;
    const int q  = t & 31;

    __shared__ float As[8][129];   // As[k][i] = w_zeta[mb*128+i][kk+k]
    __shared__ float Bs[8][128];   // Bs[k][j] = y[n][kk+k][q*128+j]

    const int tid = threadIdx.x;
    const int tx = tid & 15, ty = tid >> 4;

    float acc[8][8];
    #pragma unroll
    for (int i = 0; i < 8; i++)
        #pragma unroll
        for (int j = 0; j < 8; j++) acc[i][j] = 0.0f;

    const float* yb = g_y + (size_t)n * 128 * 4096 + q * 128;

    for (int kk = 0; kk < 128; kk += 8) {
        {
            int i = tid >> 1, kq = (tid & 1) * 4;
            float4 va = *reinterpret_cast<const float4*>(
                w_zeta + (size_t)(mb * 128 + i) * 128 + kk + kq);
            As[kq + 0][i] = va.x; As[kq + 1][i] = va.y;
            As[kq + 2][i] = va.z; As[kq + 3][i] = va.w;
        }
        {
            int k = tid >> 5, j4 = (tid & 31) * 4;
            *reinterpret_cast<float4*>(&Bs[k][j4]) =
                *reinterpret_cast<const float4*>(yb + (size_t)(kk + k) * 4096 + j4);
        }
        __syncthreads();
        #pragma unroll
        for (int k = 0; k < 8; k++) {
            float a[8], b[8];
            #pragma unroll
            for (int u = 0; u < 4; u++) {
                a[u]     = As[k][ty * 4 + u];
                a[4 + u] = As[k][64 + ty * 4 + u];
                b[u]     = Bs[k][tx * 4 + u];
                b[4 + u] = Bs[k][64 + tx * 4 + u];
            }
            #pragma unroll
            for (int i = 0; i < 8; i++)
                #pragma unroll
                for (int j = 0; j < 8; j++) acc[i][j] += a[i] * b[j];
        }
        __syncthreads();
    }

    float scale[8], shift[8];
    #pragma unroll
    for (int u = 0; u < 8; u++) {
        int i = (u < 4) ? (ty * 4 + u) : (64 + ty * 4 + (u - 4));
        int co = mb * 128 + i;
        float s = g4[co] * rsqrtf(v4[co] + BN_EPS);
        scale[u] = s;
        shift[u] = b4[co] - m4[co] * s;
    }

    #pragma unroll
    for (int ii = 0; ii < 8; ii++) {
        int i  = (ii < 4) ? (ty * 4 + ii) : (64 + ty * 4 + (ii - 4));
        int co = mb * 128 + i;
        size_t base = ((size_t)n * 256 + co) * 4096 + q * 128;
        #pragma unroll
        for (int half = 0; half < 2; half++) {
            int j0 = half * 64 + tx * 4;
            float4 xv = *reinterpret_cast<const float4*>(x + base + j0);
            float4 r;
            r.x = fmaxf(acc[ii][half * 4 + 0] * scale[ii] + shift[ii] + xv.x, 0.0f);
            r.y = fmaxf(acc[ii][half * 4 + 1] * scale[ii] + shift[ii] + xv.y, 0.0f);
            r.z = fmaxf(acc[ii][half * 4 + 2] * scale[ii] + shift[ii] + xv.z, 0.0f);
            r.w = fmaxf(acc[ii][half * 4 + 3] * scale[ii] + shift[ii] + xv.w, 0.0f);
            *reinterpret_cast<float4*>(out + base + j0) = r;
        }
    }
}

// ---------------------------------------------------------------------------
extern "C" void kernel_launch(void* const* d_in, const int* in_sizes, int n_in,
                              void* d_out, int out_size)
{
    const float* x       = (const float*)d_in[0];
    const float* w_theta = (const float*)d_in[1];
    const float* w_phi   = (const float*)d_in[2];
    const float* w_g     = (const float*)d_in[3];
    const float* w_zeta  = (const float*)d_in[4];
    const float* bn1g = (const float*)d_in[5],  *bn1b = (const float*)d_in[6];
    const float* bn1m = (const float*)d_in[7],  *bn1v = (const float*)d_in[8];
    const float* bn2g = (const float*)d_in[9],  *bn2b = (const float*)d_in[10];
    const float* bn2m = (const float*)d_in[11], *bn2v = (const float*)d_in[12];
    const float* bn3g = (const float*)d_in[13], *bn3b = (const float*)d_in[14];
    const float* bn3m = (const float*)d_in[15], *bn3v = (const float*)d_in[16];
    const float* bn4g = (const float*)d_in[17], *bn4b = (const float*)d_in[18];
    const float* bn4m = (const float*)d_in[19], *bn4v = (const float*)d_in[20];
    float* out = (float*)d_out;

    zero_kv_kernel<<<256, 256>>>();
    proj_kernel<<<dim3(512, 3), 256>>>(x, w_theta, w_phi, w_g,
                                       bn1g, bn1b, bn1m, bn1v,
                                       bn2g, bn2b, bn2m, bn2v,
                                       bn3g, bn3b, bn3m, bn3v);
    kv_kernel<<<dim3(16, 16), 256>>>();
    att_kernel<<<512, 256>>>();
    zeta_kernel<<<dim3(512, 2), 256>>>(w_zeta, x, bn4g, bn4b, bn4m, bn4v, out);
}

// round 7
// speedup vs baseline: 1.0087x; 1.0016x over previous
#include <cuda_runtime.h>

// ---------------------------------------------------------------------------
// NonlocalBlock: fused 1x1-conv non-local block, fp32 SGEMM pipeline.
// Shapes: N=16, C=256, H=W=64 (S=4096), width=128, planes=256.
//
// Pipeline (all GEMMs, 128x128 block tiles, 256 threads, 8x8 microtiles):
//   Z  : zero kv accumulator
//   A  : theta/phi/g = relu(bn(W[128x256] @ x[256xS])), stored pixel-major [n][s][c]
//   B  : kv[n] = sum_s phi[s][:]^T g[s][:]  (split-K=16, atomicAdd)
//   C1 : y[n][ch][q*128+d] = sum_c theta[n][ch*32+q][c] * kv[n][c][d]
//        (this IS the torch reshape [n,S,128]->[n,128,64,64])
//   C2 : out = relu(bn4(w_zeta[256x128] @ y) + x)
// ---------------------------------------------------------------------------

#define BN_EPS 1e-5f

// scratch (device globals: allocation-free per harness rules)
__device__ float g_theta[16 * 4096 * 128];  // [n][s][c]
__device__ float g_phi  [16 * 4096 * 128];  // [n][s][c]
__device__ float g_gbuf [16 * 4096 * 128];  // [n][s][c]
__device__ float g_kv   [16 * 128 * 128];   // [n][c][d]
__device__ float g_y    [16 * 128 * 4096];  // [n][ch][pix]

// ---------------------------------------------------------------------------
__global__ void zero_kv_kernel() {
    int idx = blockIdx.x * blockDim.x + threadIdx.x;
    const int total = 16 * 128 * 128;
    for (int i = idx; i < total; i += gridDim.x * blockDim.x) g_kv[i] = 0.0f;
}

// ---------------------------------------------------------------------------
// Kernel A: projections. grid (512 pixel tiles, 3 projections), 256 threads.
// C_out[i][j] = sum_k W[i][k] * x[n][k][p0+j], then bn+relu, store [s][c].
__global__ __launch_bounds__(256) void proj_kernel(
    const float* __restrict__ x,
    const float* __restrict__ w0, const float* __restrict__ w1, const float* __restrict__ w2,
    const float* __restrict__ g0, const float* __restrict__ b0, const float* __restrict__ m0, const float* __restrict__ v0,
    const float* __restrict__ g1, const float* __restrict__ b1, const float* __restrict__ m1, const float* __restrict__ v1,
    const float* __restrict__ g2, const float* __restrict__ b2, const float* __restrict__ m2, const float* __restrict__ v2)
{
    const int t  = blockIdx.x;       // 0..511
    const int mb = blockIdx.y;       // 0 theta, 1 phi, 2 g
    const int n  = t >> 5;
    const int q  = t & 31;

    const float* W  = (mb == 0) ? w0 : (mb == 1) ? w1 : w2;
    const float* gm = (mb == 0) ? g0 : (mb == 1) ? g1 : g2;
    const float* bt = (mb == 0) ? b0 : (mb == 1) ? b1 : b2;
    const float* mn = (mb == 0) ? m0 : (mb == 1) ? m1 : m2;
    const float* vr = (mb == 0) ? v0 : (mb == 1) ? v1 : v2;
    float* outb = (mb == 0) ? g_theta : (mb == 1) ? g_phi : g_gbuf;

    __shared__ float As[8][129];   // As[k][i] = W[i][kk+k]  (padded: scattered stores)
    __shared__ float Bs[8][128];   // Bs[k][j] = x[n][kk+k][p0+j]

    const int tid = threadIdx.x;
    const int tx = tid & 15, ty = tid >> 4;

    float acc[8][8];
    #pragma unroll
    for (int i = 0; i < 8; i++)
        #pragma unroll
        for (int j = 0; j < 8; j++) acc[i][j] = 0.0f;

    const float* xblk = x + (size_t)n * 256 * 4096 + q * 128;

    for (int kk = 0; kk < 256; kk += 8) {
        { // A tile (transpose load)
            int i = tid >> 1, kq = (tid & 1) * 4;
            float4 va = *reinterpret_cast<const float4*>(W + i * 256 + kk + kq);
            As[kq + 0][i] = va.x; As[kq + 1][i] = va.y;
            As[kq + 2][i] = va.z; As[kq + 3][i] = va.w;
        }
        { // B tile (coalesced)
            int k = tid >> 5, j4 = (tid & 31) * 4;
            *reinterpret_cast<float4*>(&Bs[k][j4]) =
                *reinterpret_cast<const float4*>(xblk + (size_t)(kk + k) * 4096 + j4);
        }
        __syncthreads();
        #pragma unroll
        for (int k = 0; k < 8; k++) {
            float a[8], b[8];
            #pragma unroll
            for (int u = 0; u < 4; u++) {
                a[u]     = As[k][ty * 4 + u];
                a[4 + u] = As[k][64 + ty * 4 + u];
                b[u]     = Bs[k][tx * 4 + u];
                b[4 + u] = Bs[k][64 + tx * 4 + u];
            }
            #pragma unroll
            for (int i = 0; i < 8; i++)
                #pragma unroll
                for (int j = 0; j < 8; j++) acc[i][j] += a[i] * b[j];
        }
        __syncthreads();
    }

    // bn scale/shift per owned row (channel)
    float scale[8], shift[8];
    #pragma unroll
    for (int u = 0; u < 8; u++) {
        int i = (u < 4) ? (ty * 4 + u) : (64 + ty * 4 + (u - 4));
        float s = gm[i] * rsqrtf(vr[i] + BN_EPS);
        scale[u] = s;
        shift[u] = bt[i] - mn[i] * s;
    }

    // store: pixel-major [s][c]; per pixel-column write two float4 in c
    float* ob = outb + ((size_t)n * 4096 + (size_t)q * 128) * 128;
    #pragma unroll
    for (int jj = 0; jj < 8; jj++) {
        int j = (jj < 4) ? (tx * 4 + jj) : (64 + tx * 4 + (jj - 4));
        float4 v0, v1;
        v0.x = fmaxf(acc[0][jj] * scale[0] + shift[0], 0.0f);
        v0.y = fmaxf(acc[1][jj] * scale[1] + shift[1], 0.0f);
        v0.z = fmaxf(acc[2][jj] * scale[2] + shift[2], 0.0f);
        v0.w = fmaxf(acc[3][jj] * scale[3] + shift[3], 0.0f);
        v1.x = fmaxf(acc[4][jj] * scale[4] + shift[4], 0.0f);
        v1.y = fmaxf(acc[5][jj] * scale[5] + shift[5], 0.0f);
        v1.z = fmaxf(acc[6][jj] * scale[6] + shift[6], 0.0f);
        v1.w = fmaxf(acc[7][jj] * scale[7] + shift[7], 0.0f);
        *reinterpret_cast<float4*>(ob + (size_t)j * 128 + ty * 4)      = v0;
        *reinterpret_cast<float4*>(ob + (size_t)j * 128 + 64 + ty * 4) = v1;
    }
}

// ---------------------------------------------------------------------------
// Kernel B: kv[n][c][d] = sum_s phi[n][s][c] * g[n][s][d]. grid (16 n, 16 splits).
__global__ __launch_bounds__(256) void kv_kernel()
{
    const int n  = blockIdx.x;
    const int s0 = blockIdx.y * 256;

    __shared__ float As[8][128];   // phi rows (K-major already)
    __shared__ float Bs[8][128];   // g rows

    const int tid = threadIdx.x;
    const int tx = tid & 15, ty = tid >> 4;

    float acc[8][8];
    #pragma unroll
    for (int i = 0; i < 8; i++)
        #pragma unroll
        for (int j = 0; j < 8; j++) acc[i][j] = 0.0f;

    const float* phib = g_phi  + ((size_t)n * 4096 + s0) * 128;
    const float* gb   = g_gbuf + ((size_t)n * 4096 + s0) * 128;

    for (int kk = 0; kk < 256; kk += 8) {
        int k = tid >> 5, c4 = (tid & 31) * 4;
        *reinterpret_cast<float4*>(&As[k][c4]) =
            *reinterpret_cast<const float4*>(phib + (size_t)(kk + k) * 128 + c4);
        *reinterpret_cast<float4*>(&Bs[k][c4]) =
            *reinterpret_cast<const float4*>(gb + (size_t)(kk + k) * 128 + c4);
        __syncthreads();
        #pragma unroll
        for (int k2 = 0; k2 < 8; k2++) {
            float a[8], b[8];
            #pragma unroll
            for (int u = 0; u < 4; u++) {
                a[u]     = As[k2][ty * 4 + u];
                a[4 + u] = As[k2][64 + ty * 4 + u];
                b[u]     = Bs[k2][tx * 4 + u];
                b[4 + u] = Bs[k2][64 + tx * 4 + u];
            }
            #pragma unroll
            for (int i = 0; i < 8; i++)
                #pragma unroll
                for (int j = 0; j < 8; j++) acc[i][j] += a[i] * b[j];
        }
        __syncthreads();
    }

    float* kvp = g_kv + (size_t)n * 16384;
    #pragma unroll
    for (int ii = 0; ii < 8; ii++) {
        int i = (ii < 4) ? (ty * 4 + ii) : (64 + ty * 4 + (ii - 4));
        #pragma unroll
        for (int jj = 0; jj < 8; jj++) {
            int j = (jj < 4) ? (tx * 4 + jj) : (64 + tx * 4 + (jj - 4));
            atomicAdd(&kvp[i * 128 + j], acc[ii][jj]);
        }
    }
}

// ---------------------------------------------------------------------------
// Kernel C1: y[n][ch][q*128+d] = sum_c theta[n][ch*32+q][c] * kv[n][c][d]. grid 512.
__global__ __launch_bounds__(256) void att_kernel()
{
    const int t = blockIdx.x;
    const int n = t >> 5;
    const int q = t & 31;

    __shared__ float Ta[8][129];   // Ta[k][ch] = theta[n][ch*32+q][c0+k]
    __shared__ float Kb[8][128];   // Kb[k][d]  = kv[n][c0+k][d]

    const int tid = threadIdx.x;
    const int tx = tid & 15, ty = tid >> 4;

    float acc[8][8];
    #pragma unroll
    for (int i = 0; i < 8; i++)
        #pragma unroll
        for (int j = 0; j < 8; j++) acc[i][j] = 0.0f;

    const float* thb = g_theta + (size_t)n * 4096 * 128;
    const float* kvb = g_kv + (size_t)n * 16384;

    for (int c0 = 0; c0 < 128; c0 += 8) {
        { // theta gather+transpose: ch = tid/2, 4 consecutive c
            int ch = tid >> 1, kq = (tid & 1) * 4;
            int s = ch * 32 + q;
            float4 va = *reinterpret_cast<const float4*>(thb + (size_t)s * 128 + c0 + kq);
            Ta[kq + 0][ch] = va.x; Ta[kq + 1][ch] = va.y;
            Ta[kq + 2][ch] = va.z; Ta[kq + 3][ch] = va.w;
        }
        {
            int k = tid >> 5, d4 = (tid & 31) * 4;
            *reinterpret_cast<float4*>(&Kb[k][d4]) =
                *reinterpret_cast<const float4*>(kvb + (size_t)(c0 + k) * 128 + d4);
        }
        __syncthreads();
        #pragma unroll
        for (int k = 0; k < 8; k++) {
            float a[8], b[8];
            #pragma unroll
            for (int u = 0; u < 4; u++) {
                a[u]     = Ta[k][ty * 4 + u];
                a[4 + u] = Ta[k][64 + ty * 4 + u];
                b[u]     = Kb[k][tx * 4 + u];
                b[4 + u] = Kb[k][64 + tx * 4 + u];
            }
            #pragma unroll
            for (int i = 0; i < 8; i++)
                #pragma unroll
                for (int j = 0; j < 8; j++) acc[i][j] += a[i] * b[j];
        }
        __syncthreads();
    }

    float* yb = g_y + (size_t)n * 128 * 4096 + q * 128;
    #pragma unroll
    for (int ii = 0; ii < 8; ii++) {
        int ch = (ii < 4) ? (ty * 4 + ii) : (64 + ty * 4 + (ii - 4));
        float4 v0 = make_float4(acc[ii][0], acc[ii][1], acc[ii][2], acc[ii][3]);
        float4 v1 = make_float4(acc[ii][4], acc[ii][5], acc[ii][6], acc[ii][7]);
        *reinterpret_cast<float4*>(yb + (size_t)ch * 4096 + tx * 4)      = v0;
        *reinterpret_cast<float4*>(yb + (size_t)ch * 4096 + 64 + tx * 4) = v1;
    }
}

// ---------------------------------------------------------------------------
// Kernel C2: out = relu(bn4(w_zeta @ y) + x). grid (512 tiles, 2 co halves).
__global__ __launch_bounds__(256) void zeta_kernel(
    const float* __restrict__ w_zeta, const float* __restrict__ x,
    const float* __restrict__ g4, const float* __restrict__ b4,
    const float* __restrict__ m4, const float* __restrict__ v4,
    float* __restrict__ out)
{
    const int t  = blockIdx.x;
    const int mb = blockIdx.y;   // output-channel half
    const int n  = t >> 5;
    const int q  = t & 31;

    __shared__ float As[8][129];   // As[k][i] = w_zeta[mb*128+i][kk+k]
    __shared__ float Bs[8][128];   // Bs[k][j] = y[n][kk+k][q*128+j]

    const int tid = threadIdx.x;
    const int tx = tid & 15, ty = tid >> 4;

    float acc[8][8];
    #pragma unroll
    for (int i = 0; i < 8; i++)
        #pragma unroll
        for (int j = 0; j < 8; j++) acc[i][j] = 0.0f;

    const float* yb = g_y + (size_t)n * 128 * 4096 + q * 128;

    for (int kk = 0; kk < 128; kk += 8) {
        {
            int i = tid >> 1, kq = (tid & 1) * 4;
            float4 va = *reinterpret_cast<const float4*>(
                w_zeta + (size_t)(mb * 128 + i) * 128 + kk + kq);
            As[kq + 0][i] = va.x; As[kq + 1][i] = va.y;
            As[kq + 2][i] = va.z; As[kq + 3][i] = va.w;
        }
        {
            int k = tid >> 5, j4 = (tid & 31) * 4;
            *reinterpret_cast<float4*>(&Bs[k][j4]) =
                *reinterpret_cast<const float4*>(yb + (size_t)(kk + k) * 4096 + j4);
        }
        __syncthreads();
        #pragma unroll
        for (int k = 0; k < 8; k++) {
            float a[8], b[8];
            #pragma unroll
            for (int u = 0; u < 4; u++) {
                a[u]     = As[k][ty * 4 + u];
                a[4 + u] = As[k][64 + ty * 4 + u];
                b[u]     = Bs[k][tx * 4 + u];
                b[4 + u] = Bs[k][64 + tx * 4 + u];
            }
            #pragma unroll
            for (int i = 0; i < 8; i++)
                #pragma unroll
                for (int j = 0; j < 8; j++) acc[i][j] += a[i] * b[j];
        }
        __syncthreads();
    }

    float scale[8], shift[8];
    #pragma unroll
    for (int u = 0; u < 8; u++) {
        int i = (u < 4) ? (ty * 4 + u) : (64 + ty * 4 + (u - 4));
        int co = mb * 128 + i;
        float s = g4[co] * rsqrtf(v4[co] + BN_EPS);
        scale[u] = s;
        shift[u] = b4[co] - m4[co] * s;
    }

    #pragma unroll
    for (int ii = 0; ii < 8; ii++) {
        int i  = (ii < 4) ? (ty * 4 + ii) : (64 + ty * 4 + (ii - 4));
        int co = mb * 128 + i;
        size_t base = ((size_t)n * 256 + co) * 4096 + q * 128;
        #pragma unroll
        for (int half = 0; half < 2; half++) {
            int j0 = half * 64 + tx * 4;
            float4 xv = *reinterpret_cast<const float4*>(x + base + j0);
            float4 r;
            r.x = fmaxf(acc[ii][half * 4 + 0] * scale[ii] + shift[ii] + xv.x, 0.0f);
            r.y = fmaxf(acc[ii][half * 4 + 1] * scale[ii] + shift[ii] + xv.y, 0.0f);
            r.z = fmaxf(acc[ii][half * 4 + 2] * scale[ii] + shift[ii] + xv.z, 0.0f);
            r.w = fmaxf(acc[ii][half * 4 + 3] * scale[ii] + shift[ii] + xv.w, 0.0f);
            *reinterpret_cast<float4*>(out + base + j0) = r;
        }
    }
}

// ---------------------------------------------------------------------------
extern "C" void kernel_launch(void* const* d_in, const int* in_sizes, int n_in,
                              void* d_out, int out_size)
{
    const float* x       = (const float*)d_in[0];
    const float* w_theta = (const float*)d_in[1];
    const float* w_phi   = (const float*)d_in[2];
    const float* w_g     = (const float*)d_in[3];
    const float* w_zeta  = (const float*)d_in[4];
    const float* bn1g = (const float*)d_in[5],  *bn1b = (const float*)d_in[6];
    const float* bn1m = (const float*)d_in[7],  *bn1v = (const float*)d_in[8];
    const float* bn2g = (const float*)d_in[9],  *bn2b = (const float*)d_in[10];
    const float* bn2m = (const float*)d_in[11], *bn2v = (const float*)d_in[12];
    const float* bn3g = (const float*)d_in[13], *bn3b = (const float*)d_in[14];
    const float* bn3m = (const float*)d_in[15], *bn3v = (const float*)d_in[16];
    const float* bn4g = (const float*)d_in[17], *bn4b = (const float*)d_in[18];
    const float* bn4m = (const float*)d_in[19], *bn4v = (const float*)d_in[20];
    float* out = (float*)d_out;

    zero_kv_kernel<<<256, 256>>>();
    proj_kernel<<<dim3(512, 3), 256>>>(x, w_theta, w_phi, w_g,
                                       bn1g, bn1b, bn1m, bn1v,
                                       bn2g, bn2b, bn2m, bn2v,
                                       bn3g, bn3b, bn3m, bn3v);
    kv_kernel<<<dim3(16, 16), 256>>>();
    att_kernel<<<512, 256>>>();
    zeta_kernel<<<dim3(512, 2), 256>>>(w_zeta, x, bn4g, bn4b, bn4m, bn4v, out);
}